// round 1
// baseline (speedup 1.0000x reference)
#include <cuda_runtime.h>
#include <math.h>

#define NB 8
#define NJ 17
#define NV 64
#define NPAIR (NB * NJ)            // 136
#define VOX (NV * NV * NV)         // 262144
#define SPLIT 16
#define THREADS 256
#define CHUNK (VOX / SPLIT)        // 16384 elements per block
#define ITERS (CHUNK / 4 / THREADS) // 16 float4 per thread

__device__ float g_partials[NPAIR * SPLIT];

__global__ __launch_bounds__(THREADS) void sumexp_kernel(const float* __restrict__ vol) {
    const int blk  = blockIdx.x;           // 0 .. NPAIR*SPLIT-1
    const int pair = blk / SPLIT;
    const int part = blk % SPLIT;

    const float4* base = reinterpret_cast<const float4*>(
        vol + (size_t)pair * VOX + (size_t)part * CHUNK);

    float s = 0.0f;
#pragma unroll
    for (int i = 0; i < ITERS; ++i) {
        float4 v = __ldg(base + i * THREADS + threadIdx.x);
        s += __expf(v.x) + __expf(v.y) + __expf(v.z) + __expf(v.w);
    }

    // warp reduce
#pragma unroll
    for (int off = 16; off > 0; off >>= 1)
        s += __shfl_down_sync(0xFFFFFFFFu, s, off);

    __shared__ float sh[THREADS / 32];
    const int lane = threadIdx.x & 31;
    const int wid  = threadIdx.x >> 5;
    if (lane == 0) sh[wid] = s;
    __syncthreads();

    if (wid == 0) {
        float v = (lane < THREADS / 32) ? sh[lane] : 0.0f;
#pragma unroll
        for (int off = 4; off > 0; off >>= 1)
            v += __shfl_down_sync(0xFFFFFFFFu, v, off);
        if (lane == 0) g_partials[blk] = v;
    }
}

__device__ __forceinline__ int grid_idx(float l, float c) {
    float norm = (l - c) * (1.0f / 1000.0f);        // box_range = 1000
    int idx = (int)floorf((norm + 1.0f) * 0.5f * (float)(NV - 1));
    idx = idx < 0 ? 0 : (idx > NV - 1 ? NV - 1 : idx);
    return idx;
}

__global__ __launch_bounds__(256) void finalize_kernel(const float* __restrict__ vol,
                                                       const float* __restrict__ label,
                                                       const float* __restrict__ center,
                                                       float* __restrict__ out) {
    __shared__ float sh[256];
    const int t = threadIdx.x;

    float term = 0.0f;
    if (t < NPAIR) {
        const int b = t / NJ;
        // combine split partials
        float S = 0.0f;
#pragma unroll
        for (int k = 0; k < SPLIT; ++k)
            S += g_partials[t * SPLIT + k];

        const float cx = center[b * 3 + 0];
        const float cy = center[b * 3 + 1];
        const float cz = center[b * 3 + 2];
        const float lx = label[t * 3 + 0];
        const float ly = label[t * 3 + 1];
        const float lz = label[t * 3 + 2];

        const int ix = grid_idx(lx, cx);
        const int iy = grid_idx(ly, cy);
        const int iz = grid_idx(lz, cz);
        const int flat = (ix * NV + iy) * NV + iz;

        const float x = vol[(size_t)t * VOX + flat];
        const float p = __expf(x) / S;
        term = -logf(p + 1e-6f) * 0.01f;   // beta = 0.01
    }

    sh[t] = term;
    __syncthreads();
#pragma unroll
    for (int s = 128; s > 0; s >>= 1) {
        if (t < s) sh[t] += sh[t + s];
        __syncthreads();
    }
    if (t == 0) out[0] = sh[0] * (1.0f / (float)NPAIR);
}

extern "C" void kernel_launch(void* const* d_in, const int* in_sizes, int n_in,
                              void* d_out, int out_size) {
    const float* vol    = (const float*)d_in[0];
    const float* label  = (const float*)d_in[1];
    const float* center = (const float*)d_in[2];
    float* out = (float*)d_out;

    sumexp_kernel<<<NPAIR * SPLIT, THREADS>>>(vol);
    finalize_kernel<<<1, 256>>>(vol, label, center, out);
}